// round 11
// baseline (speedup 1.0000x reference)
#include <cuda_runtime.h>
#include <cuda_bf16.h>
#include <cstdint>

#define BB 2
#define LL 2048
#define DD 1024
#define HH 16
#define HD 64
#define MM (BB*LL)          // 4096
#define E3 (3*DD)           // 3072
#define PH (DD/2)           // 512
#define GK DD               // GEMM K=1024

typedef unsigned long long ull;
typedef __nv_bfloat16 bf16;

// ---------------- scratch ----------------
__device__ float g_qkv[MM * E3];
__device__ float g_phases[MM * PH];
__device__ bf16 g_xh[MM*DD],  g_xl[MM*DD];
__device__ bf16 g_wqh[E3*DD], g_wql[E3*DD];
__device__ bf16 g_ph2[MM*DD], g_pl2[MM*DD];
__device__ bf16 g_pth[PH*DD], g_ptl[PH*DD];
__device__ bf16 g_oh[MM*DD],  g_ol[MM*DD];
__device__ bf16 g_woh[DD*DD], g_wol[DD*DD];
__device__ bf16 g_qh[MM*DD], g_ql[MM*DD];
__device__ bf16 g_kh[MM*DD], g_kl[MM*DD];
__device__ bf16 g_vh[MM*DD], g_vl[MM*DD];

// ---------------- PTX helpers ----------------
__device__ __forceinline__ uint32_t smem_u32(const void* p) {
    uint32_t a;
    asm("{ .reg .u64 t; cvta.to.shared.u64 t, %1; cvt.u32.u64 %0, t; }" : "=r"(a) : "l"(p));
    return a;
}
#define LDSM4(R, addr) \
    asm volatile("ldmatrix.sync.aligned.m8n8.x4.shared.b16 {%0,%1,%2,%3}, [%4];" \
        : "=r"((R)[0]), "=r"((R)[1]), "=r"((R)[2]), "=r"((R)[3]) : "r"(addr))
#define LDSM4T(R, addr) \
    asm volatile("ldmatrix.sync.aligned.m8n8.x4.trans.shared.b16 {%0,%1,%2,%3}, [%4];" \
        : "=r"((R)[0]), "=r"((R)[1]), "=r"((R)[2]), "=r"((R)[3]) : "r"(addr))
#define MMA16816(D, A, B0, B1) \
    asm volatile("mma.sync.aligned.m16n8k16.row.col.f32.bf16.bf16.f32 " \
        "{%0,%1,%2,%3}, {%4,%5,%6,%7}, {%8,%9}, {%0,%1,%2,%3};" \
        : "+f"((D)[0]), "+f"((D)[1]), "+f"((D)[2]), "+f"((D)[3]) \
        : "r"((A)[0]), "r"((A)[1]), "r"((A)[2]), "r"((A)[3]), "r"(B0), "r"(B1))
#define CPA16(dst, src) \
    asm volatile("cp.async.cg.shared.global [%0], [%1], 16;" :: "r"(dst), "l"(src))
#define CPA_COMMIT() asm volatile("cp.async.commit_group;" ::: "memory")
#define CPA_WAIT1()  asm volatile("cp.async.wait_group 1;" ::: "memory")
#define CPA_WAIT0()  asm volatile("cp.async.wait_group 0;" ::: "memory")

union BF2U { __nv_bfloat162 b; uint32_t u; };
__device__ __forceinline__ void split_pack2(float e0, float e1, uint32_t& hi, uint32_t& lo) {
    bf16 h0 = __float2bfloat16(e0), h1 = __float2bfloat16(e1);
    float r0 = e0 - __bfloat162float(h0), r1 = e1 - __bfloat162float(h1);
    BF2U a, b2;
    a.b  = __halves2bfloat162(h0, h1);
    b2.b = __halves2bfloat162(__float2bfloat16(r0), __float2bfloat16(r1));
    hi = a.u; lo = b2.u;
}

// ---------------------------------------------------------------------------
// fp32 -> (hi, lo) bf16 split, 4 elems/thread
// ---------------------------------------------------------------------------
__global__ void split_bf16(const float* __restrict__ src,
                           bf16* __restrict__ hi, bf16* __restrict__ lo, int n)
{
    int i = (blockIdx.x * blockDim.x + threadIdx.x) * 4;
    if (i < n) {
        float4 v = *(const float4*)(src + i);
        uint32_t h0, l0, h1, l1;
        split_pack2(v.x, v.y, h0, l0);
        split_pack2(v.z, v.w, h1, l1);
        *(uint2*)(hi + i) = make_uint2(h0, h1);
        *(uint2*)(lo + i) = make_uint2(l0, l1);
    }
}

// proj (D, PH) -> transposed split (PH, D) in one pass
__global__ void split_projT(const float* __restrict__ proj,
                            bf16* __restrict__ hi, bf16* __restrict__ lo)
{
    int idx = blockIdx.x * blockDim.x + threadIdx.x;   // PH*DD
    int j = idx >> 10;
    int d = idx & 1023;
    float v = proj[(size_t)d * PH + j];
    bf16 h = __float2bfloat16(v);
    hi[idx] = h;
    lo[idx] = __float2bfloat16(v - __bfloat162float(h));
}

// ---------------------------------------------------------------------------
// HMMA NT GEMM: C = A @ B^T (+bias). Term-major ordering,
// 3-stage cp.async pipeline, ONE __syncthreads per k-iteration.
// ---------------------------------------------------------------------------
#define PITCH 40
#define BUF_B (128 * PITCH * 2)
#define STAGE_B (4 * BUF_B)             // 40960
#define NSTG 3
#define GEMM_SMEM (NSTG * STAGE_B)      // 122880
#define NKC (GK / 32)                   // 32

__global__ __launch_bounds__(256) void gemm_mma(
    const bf16* __restrict__ Ahi, const bf16* __restrict__ Alo,
    const bf16* __restrict__ Bhi, const bf16* __restrict__ Blo,
    const float* __restrict__ bias, float* __restrict__ C, int N)
{
    extern __shared__ char smem[];
    const uint32_t sb = smem_u32(smem);
    const int tid = threadIdx.x;
    const int lane = tid & 31;
    const int wid = tid >> 5;
    const int warp_m = wid >> 1;
    const int warp_n = wid & 1;
    const int bm = blockIdx.y * 128;
    const int bn = blockIdx.x * 128;

    const int lr = tid >> 1;
    const int lh = tid & 1;
    const bf16* gAh = Ahi + (size_t)(bm + lr) * GK + lh * 16;
    const bf16* gAl = Alo + (size_t)(bm + lr) * GK + lh * 16;
    const bf16* gBh = Bhi + (size_t)(bn + lr) * GK + lh * 16;
    const bf16* gBl = Blo + (size_t)(bn + lr) * GK + lh * 16;
    const uint32_t srow = sb + (uint32_t)(lr * PITCH + lh * 16) * 2;

    auto issue_stage = [&](int kc, int s) {
        const uint32_t st = srow + s * STAGE_B;
        const size_t go = (size_t)kc * 32;
        CPA16(st + 0 * BUF_B,      gAh + go);
        CPA16(st + 0 * BUF_B + 16, gAh + go + 8);
        CPA16(st + 1 * BUF_B,      gAl + go);
        CPA16(st + 1 * BUF_B + 16, gAl + go + 8);
        CPA16(st + 2 * BUF_B,      gBh + go);
        CPA16(st + 2 * BUF_B + 16, gBh + go + 8);
        CPA16(st + 3 * BUF_B,      gBl + go);
        CPA16(st + 3 * BUF_B + 16, gBl + go + 8);
    };

    float acc[2][8][4];
    #pragma unroll
    for (int mt = 0; mt < 2; mt++)
        #pragma unroll
        for (int nt = 0; nt < 8; nt++)
            #pragma unroll
            for (int e = 0; e < 4; e++) acc[mt][nt][e] = 0.f;

    const int lrow = lane & 15;
    const int lsub = lane >> 4;

    issue_stage(0, 0);
    CPA_COMMIT();
    issue_stage(1, 1);
    CPA_COMMIT();

    int cur = 0;
    for (int kc = 0; kc < NKC; kc++) {
        if (kc < NKC - 1) { CPA_WAIT1(); } else { CPA_WAIT0(); }
        __syncthreads();
        if (kc + 2 < NKC) {
            int s = cur + 2; if (s >= NSTG) s -= NSTG;
            issue_stage(kc + 2, s);
            CPA_COMMIT();
        }

        const uint32_t stA_hi = sb + cur * STAGE_B;
        const uint32_t stA_lo = stA_hi + BUF_B;
        const uint32_t stB_hi = stA_hi + 2 * BUF_B;
        const uint32_t stB_lo = stA_hi + 3 * BUF_B;

        #pragma unroll
        for (int h = 0; h < 2; h++) {
            const uint32_t coff = (uint32_t)(h * 16 + lsub * 8) * 2;
            uint32_t ah[2][4], al[2][4];
            #pragma unroll
            for (int mt = 0; mt < 2; mt++) {
                const uint32_t ro = (uint32_t)((warp_m * 32 + mt * 16 + lrow) * PITCH) * 2 + coff;
                LDSM4(ah[mt], stA_hi + ro);
                LDSM4(al[mt], stA_lo + ro);
            }
            uint32_t bh[4][4], bl[4][4];
            #pragma unroll
            for (int g = 0; g < 4; g++) {
                const uint32_t ro = (uint32_t)((warp_n * 64 + g * 16 + lrow) * PITCH) * 2 + coff;
                LDSM4(bh[g], stB_hi + ro);
                LDSM4(bl[g], stB_lo + ro);
            }
            #pragma unroll
            for (int mt = 0; mt < 2; mt++)
                #pragma unroll
                for (int g = 0; g < 4; g++)
                    #pragma unroll
                    for (int s2 = 0; s2 < 2; s2++)
                        MMA16816(acc[mt][g * 2 + s2], ah[mt], bh[g][s2], bh[g][s2 + 2]);
            #pragma unroll
            for (int mt = 0; mt < 2; mt++)
                #pragma unroll
                for (int g = 0; g < 4; g++)
                    #pragma unroll
                    for (int s2 = 0; s2 < 2; s2++)
                        MMA16816(acc[mt][g * 2 + s2], ah[mt], bl[g][s2], bl[g][s2 + 2]);
            #pragma unroll
            for (int mt = 0; mt < 2; mt++)
                #pragma unroll
                for (int g = 0; g < 4; g++)
                    #pragma unroll
                    for (int s2 = 0; s2 < 2; s2++)
                        MMA16816(acc[mt][g * 2 + s2], al[mt], bh[g][s2], bh[g][s2 + 2]);
        }
        cur++; if (cur == NSTG) cur = 0;
    }

    const int gid = lane >> 2;
    const int tig = lane & 3;
    #pragma unroll
    for (int mt = 0; mt < 2; mt++) {
        const int r0 = bm + warp_m * 32 + mt * 16 + gid;
        #pragma unroll
        for (int nt = 0; nt < 8; nt++) {
            const int c0 = bn + warp_n * 64 + nt * 8 + tig * 2;
            float b0 = bias ? bias[c0] : 0.f;
            float b1 = bias ? bias[c0 + 1] : 0.f;
            *(float2*)&C[(size_t)r0 * N + c0] =
                make_float2(acc[mt][nt][0] + b0, acc[mt][nt][1] + b1);
            *(float2*)&C[(size_t)(r0 + 8) * N + c0] =
                make_float2(acc[mt][nt][2] + b0, acc[mt][nt][3] + b1);
        }
    }
}

// ---------------------------------------------------------------------------
// RoPE + split, vectorized: 2 columns per thread.
// ---------------------------------------------------------------------------
__global__ void rope_split(const float* __restrict__ qkv, const float* __restrict__ phases,
                           bf16* __restrict__ qh, bf16* __restrict__ ql,
                           bf16* __restrict__ kh, bf16* __restrict__ kl,
                           bf16* __restrict__ vh, bf16* __restrict__ vl)
{
    int idx = blockIdx.x * blockDim.x + threadIdx.x;   // MM*PH/2
    int m = idx >> 8;
    int r = idx & 255;
    int h = r >> 4;
    int j0 = (r & 15) * 2;
    const float2 ph2 = *(const float2*)(phases + (size_t)m * PH + h * 32 + j0);
    float s0, c0, s1, c1;
    __sincosf(ph2.x, &s0, &c0);
    __sincosf(ph2.y, &s1, &c1);
    size_t ib = (size_t)m * E3 + h * HD + j0;
    size_t ob = (size_t)m * DD + h * HD + j0;
    uint32_t hi, lo;

    float2 q1 = *(const float2*)(qkv + ib);
    float2 q2 = *(const float2*)(qkv + ib + 32);
    split_pack2((q1.x * c0 - q2.x * s0) * 0.125f, (q1.y * c1 - q2.y * s1) * 0.125f, hi, lo);
    *(uint32_t*)(qh + ob) = hi; *(uint32_t*)(ql + ob) = lo;
    split_pack2((q1.x * s0 + q2.x * c0) * 0.125f, (q1.y * s1 + q2.y * c1) * 0.125f, hi, lo);
    *(uint32_t*)(qh + ob + 32) = hi; *(uint32_t*)(ql + ob + 32) = lo;

    float2 k1 = *(const float2*)(qkv + ib + DD);
    float2 k2 = *(const float2*)(qkv + ib + DD + 32);
    split_pack2(k1.x * c0 - k2.x * s0, k1.y * c1 - k2.y * s1, hi, lo);
    *(uint32_t*)(kh + ob) = hi; *(uint32_t*)(kl + ob) = lo;
    split_pack2(k1.x * s0 + k2.x * c0, k1.y * s1 + k2.y * c1, hi, lo);
    *(uint32_t*)(kh + ob + 32) = hi; *(uint32_t*)(kl + ob + 32) = lo;

    float2 v1 = *(const float2*)(qkv + ib + 2 * DD);
    float2 v2 = *(const float2*)(qkv + ib + 2 * DD + 32);
    split_pack2(v1.x, v1.y, hi, lo);
    *(uint32_t*)(vh + ob) = hi; *(uint32_t*)(vl + ob) = lo;
    split_pack2(v2.x, v2.y, hi, lo);
    *(uint32_t*)(vh + ob + 32) = hi; *(uint32_t*)(vl + ob + 32) = lo;
}

// ---------------------------------------------------------------------------
// HMMA flash attention (unchanged)
// ---------------------------------------------------------------------------
#define FROWB 144
#define FQH 0
#define FQL 18432
#define FKV 36864
#define FSTG 36864
#define F_KH 0
#define F_KL 9216
#define F_VH 18432
#define F_VL 27648
#define FLASH_SMEM (FKV + 2 * FSTG)   // 110592 B

__global__ __launch_bounds__(256) void flash_mma(
    const bf16* __restrict__ qh_g, const bf16* __restrict__ ql_g,
    const bf16* __restrict__ kh_g, const bf16* __restrict__ kl_g,
    const bf16* __restrict__ vh_g, const bf16* __restrict__ vl_g,
    bf16* __restrict__ oh_g, bf16* __restrict__ ol_g)
{
    extern __shared__ char smem[];
    const uint32_t sb = smem_u32(smem);
    const int tid = threadIdx.x;
    const int lane = tid & 31;
    const int warp = tid >> 5;
    const int b = blockIdx.z, h = blockIdx.y, qt = blockIdx.x;

    const size_t qrow0 = (size_t)b * LL + qt * 128;
    const size_t krow0 = (size_t)b * LL;
    const int hcol = h * HD;

    const int qlr = tid >> 1;
    const int qlc = (tid & 1) * 4;
    const uint32_t qdst = (uint32_t)(qlr * FROWB + qlc * 16);
    const size_t qsrc = (size_t)qlr * DD + hcol + qlc * 8;
    const int klr = tid >> 2;
    const int klc = (tid & 3) * 2;
    const uint32_t kdst = (uint32_t)(klr * FROWB + klc * 16);
    const size_t ksrc = (size_t)klr * DD + hcol + klc * 8;

    auto issue_kv = [&](int kt, int s) {
        const uint32_t st = sb + FKV + s * FSTG + kdst;
        const size_t go = (size_t)kt * 64 * DD + krow0 * DD + ksrc;
        CPA16(st + F_KH,      kh_g + go);
        CPA16(st + F_KH + 16, kh_g + go + 8);
        CPA16(st + F_KL,      kl_g + go);
        CPA16(st + F_KL + 16, kl_g + go + 8);
        CPA16(st + F_VH,      vh_g + go);
        CPA16(st + F_VH + 16, vh_g + go + 8);
        CPA16(st + F_VL,      vl_g + go);
        CPA16(st + F_VL + 16, vl_g + go + 8);
    };

    {
        const bf16* s0 = qh_g + qrow0 * DD + qsrc;
        const bf16* s1 = ql_g + qrow0 * DD + qsrc;
        CPA16(sb + FQH + qdst,      s0);      CPA16(sb + FQH + qdst + 16, s0 + 8);
        CPA16(sb + FQH + qdst + 32, s0 + 16); CPA16(sb + FQH + qdst + 48, s0 + 24);
        CPA16(sb + FQL + qdst,      s1);      CPA16(sb + FQL + qdst + 16, s1 + 8);
        CPA16(sb + FQL + qdst + 32, s1 + 16); CPA16(sb + FQL + qdst + 48, s1 + 24);
    }
    issue_kv(0, 0);
    CPA_COMMIT();

    const int lrow = lane & 15;
    const int lsub = lane >> 4;
    const int gid = lane >> 2;
    const int tig = lane & 3;

    uint32_t qfh[4][4], qfl[4][4];
    float o[8][4];
    #pragma unroll
    for (int nt = 0; nt < 8; nt++)
        #pragma unroll
        for (int e = 0; e < 4; e++) o[nt][e] = 0.f;
    float m_a = -1e30f, m_b = -1e30f, l_a = 0.f, l_b = 0.f;

    for (int kt = 0; kt < LL / 64; kt++) {
        const int cur = kt & 1;
        if (kt + 1 < LL / 64) {
            issue_kv(kt + 1, cur ^ 1);
            CPA_COMMIT();
            CPA_WAIT1();
        } else {
            CPA_WAIT0();
        }
        __syncthreads();

        if (kt == 0) {
            #pragma unroll
            for (int ks = 0; ks < 4; ks++) {
                const uint32_t ro = (uint32_t)((warp * 16 + lrow) * FROWB + (ks * 16 + lsub * 8) * 2);
                LDSM4(qfh[ks], sb + FQH + ro);
                LDSM4(qfl[ks], sb + FQL + ro);
            }
        }

        const uint32_t kb = sb + FKV + cur * FSTG;

        float s[8][4];
        #pragma unroll
        for (int nt = 0; nt < 8; nt++)
            #pragma unroll
            for (int e = 0; e < 4; e++) s[nt][e] = 0.f;

        #pragma unroll
        for (int ks = 0; ks < 4; ks++) {
            uint32_t kfh[4][4], kfl[4][4];
            #pragma unroll
            for (int kg = 0; kg < 4; kg++) {
                const uint32_t ro = (uint32_t)((kg * 16 + lrow) * FROWB + (ks * 16 + lsub * 8) * 2);
                LDSM4(kfh[kg], kb + F_KH + ro);
                LDSM4(kfl[kg], kb + F_KL + ro);
            }
            #pragma unroll
            for (int kg = 0; kg < 4; kg++) {
                MMA16816(s[2 * kg],     qfh[ks], kfh[kg][0], kfh[kg][2]);
                MMA16816(s[2 * kg + 1], qfh[ks], kfh[kg][1], kfh[kg][3]);
            }
            #pragma unroll
            for (int kg = 0; kg < 4; kg++) {
                MMA16816(s[2 * kg],     qfh[ks], kfl[kg][0], kfl[kg][2]);
                MMA16816(s[2 * kg + 1], qfh[ks], kfl[kg][1], kfl[kg][3]);
            }
            #pragma unroll
            for (int kg = 0; kg < 4; kg++) {
                MMA16816(s[2 * kg],     qfl[ks], kfh[kg][0], kfh[kg][2]);
                MMA16816(s[2 * kg + 1], qfl[ks], kfh[kg][1], kfh[kg][3]);
            }
        }

        float mx_a = -1e30f, mx_b = -1e30f;
        #pragma unroll
        for (int nt = 0; nt < 8; nt++) {
            mx_a = fmaxf(mx_a, fmaxf(s[nt][0], s[nt][1]));
            mx_b = fmaxf(mx_b, fmaxf(s[nt][2], s[nt][3]));
        }
        #pragma unroll
        for (int off = 1; off <= 2; off <<= 1) {
            mx_a = fmaxf(mx_a, __shfl_xor_sync(0xffffffffu, mx_a, off));
            mx_b = fmaxf(mx_b, __shfl_xor_sync(0xffffffffu, mx_b, off));
        }
        const float mn_a = fmaxf(m_a, mx_a);
        const float mn_b = fmaxf(m_b, mx_b);
        const float sf_a = __expf(m_a - mn_a);
        const float sf_b = __expf(m_b - mn_b);
        m_a = mn_a; m_b = mn_b;

        float rs_a = 0.f, rs_b = 0.f;
        #pragma unroll
        for (int nt = 0; nt < 8; nt++) {
            s[nt][0] = __expf(s[nt][0] - mn_a);
            s[nt][1] = __expf(s[nt][1] - mn_a);
            s[nt][2] = __expf(s[nt][2] - mn_b);
            s[nt][3] = __expf(s[nt][3] - mn_b);
            rs_a += s[nt][0] + s[nt][1];
            rs_b += s[nt][2] + s[nt][3];
        }
        #pragma unroll
        for (int off = 1; off <= 2; off <<= 1) {
            rs_a += __shfl_xor_sync(0xffffffffu, rs_a, off);
            rs_b += __shfl_xor_sync(0xffffffffu, rs_b, off);
        }
        l_a = l_a * sf_a + rs_a;
        l_b = l_b * sf_b + rs_b;
        #pragma unroll
        for (int nt = 0; nt < 8; nt++) {
            o[nt][0] *= sf_a; o[nt][1] *= sf_a;
            o[nt][2] *= sf_b; o[nt][3] *= sf_b;
        }

        uint32_t ph[4][4], pl[4][4];
        #pragma unroll
        for (int kg = 0; kg < 4; kg++) {
            split_pack2(s[2 * kg][0],     s[2 * kg][1],     ph[kg][0], pl[kg][0]);
            split_pack2(s[2 * kg][2],     s[2 * kg][3],     ph[kg][1], pl[kg][1]);
            split_pack2(s[2 * kg + 1][0], s[2 * kg + 1][1], ph[kg][2], pl[kg][2]);
            split_pack2(s[2 * kg + 1][2], s[2 * kg + 1][3], ph[kg][3], pl[kg][3]);
        }

        #pragma unroll
        for (int kg = 0; kg < 4; kg++) {
            uint32_t vfh[4][4], vfl[4][4];
            #pragma unroll
            for (int dg = 0; dg < 4; dg++) {
                const uint32_t ro = (uint32_t)((kg * 16 + lrow) * FROWB + (dg * 16 + lsub * 8) * 2);
                LDSM4T(vfh[dg], kb + F_VH + ro);
                LDSM4T(vfl[dg], kb + F_VL + ro);
            }
            #pragma unroll
            for (int dg = 0; dg < 4; dg++) {
                MMA16816(o[2 * dg],     ph[kg], vfh[dg][0], vfh[dg][1]);
                MMA16816(o[2 * dg + 1], ph[kg], vfh[dg][2], vfh[dg][3]);
            }
            #pragma unroll
            for (int dg = 0; dg < 4; dg++) {
                MMA16816(o[2 * dg],     ph[kg], vfl[dg][0], vfl[dg][1]);
                MMA16816(o[2 * dg + 1], ph[kg], vfl[dg][2], vfl[dg][3]);
            }
            #pragma unroll
            for (int dg = 0; dg < 4; dg++) {
                MMA16816(o[2 * dg],     pl[kg], vfh[dg][0], vfh[dg][1]);
                MMA16816(o[2 * dg + 1], pl[kg], vfh[dg][2], vfh[dg][3]);
            }
        }
        __syncthreads();
    }

    const float inv_a = 1.0f / l_a;
    const float inv_b = 1.0f / l_b;
    const size_t row_a = qrow0 + warp * 16 + gid;
    const size_t row_b = row_a + 8;
    #pragma unroll
    for (int nt = 0; nt < 8; nt++) {
        const int col = hcol + nt * 8 + tig * 2;
        uint32_t hi, lo;
        split_pack2(o[nt][0] * inv_a, o[nt][1] * inv_a, hi, lo);
        *(uint32_t*)(oh_g + row_a * DD + col) = hi;
        *(uint32_t*)(ol_g + row_a * DD + col) = lo;
        split_pack2(o[nt][2] * inv_b, o[nt][3] * inv_b, hi, lo);
        *(uint32_t*)(oh_g + row_b * DD + col) = hi;
        *(uint32_t*)(ol_g + row_b * DD + col) = lo;
    }
}

// ---------------------------------------------------------------------------
extern "C" void kernel_launch(void* const* d_in, const int* in_sizes, int n_in,
                              void* d_out, int out_size)
{
    const float* x     = (const float*)d_in[0];
    const float* p     = (const float*)d_in[1];
    const float* W_qkv = (const float*)d_in[2];
    const float* b_qkv = (const float*)d_in[3];
    const float* W_out = (const float*)d_in[4];
    const float* b_out = (const float*)d_in[5];
    const float* proj  = (const float*)d_in[6];
    float* out = (float*)d_out;

    float *qkv, *phases;
    cudaGetSymbolAddress((void**)&qkv,    g_qkv);
    cudaGetSymbolAddress((void**)&phases, g_phases);
    bf16 *xh, *xl, *wqh, *wql, *ph2, *pl2, *pth, *ptl, *oh, *ol, *woh, *wol;
    bf16 *qh, *ql, *kh, *kl, *vh, *vl;
    cudaGetSymbolAddress((void**)&xh,  g_xh);  cudaGetSymbolAddress((void**)&xl,  g_xl);
    cudaGetSymbolAddress((void**)&wqh, g_wqh); cudaGetSymbolAddress((void**)&wql, g_wql);
    cudaGetSymbolAddress((void**)&ph2, g_ph2); cudaGetSymbolAddress((void**)&pl2, g_pl2);
    cudaGetSymbolAddress((void**)&pth, g_pth); cudaGetSymbolAddress((void**)&ptl, g_ptl);
    cudaGetSymbolAddress((void**)&oh,  g_oh);  cudaGetSymbolAddress((void**)&ol,  g_ol);
    cudaGetSymbolAddress((void**)&woh, g_woh); cudaGetSymbolAddress((void**)&wol, g_wol);
    cudaGetSymbolAddress((void**)&qh, g_qh); cudaGetSymbolAddress((void**)&ql, g_ql);
    cudaGetSymbolAddress((void**)&kh, g_kh); cudaGetSymbolAddress((void**)&kl, g_kl);
    cudaGetSymbolAddress((void**)&vh, g_vh); cudaGetSymbolAddress((void**)&vl, g_vl);

    cudaFuncSetAttribute(gemm_mma, cudaFuncAttributeMaxDynamicSharedMemorySize, GEMM_SMEM);
    cudaFuncSetAttribute(flash_mma, cudaFuncAttributeMaxDynamicSharedMemorySize, FLASH_SMEM);

    // launches 1-3: splits feeding the QKV GEMM
    split_bf16<<<(MM * DD) / 1024, 256>>>(x, xh, xl, MM * DD);
    split_bf16<<<(E3 * DD) / 1024, 256>>>(W_qkv, wqh, wql, E3 * DD);
    split_bf16<<<(MM * DD) / 1024, 256>>>(p, ph2, pl2, MM * DD);

    // launch 4 (profiled slot): QKV GEMM
    gemm_mma<<<dim3(E3 / 128, MM / 128), 256, GEMM_SMEM>>>(xh, xl, wqh, wql, b_qkv, qkv, E3);

    // 5-6: proj split + phases GEMM
    split_projT<<<(PH * DD) / 256, 256>>>(proj, pth, ptl);
    gemm_mma<<<dim3(PH / 128, MM / 128), 256, GEMM_SMEM>>>(ph2, pl2, pth, ptl, nullptr, phases, PH);

    // 7: rope + split
    rope_split<<<(MM * PH / 2) / 256, 256>>>(qkv, phases, qh, ql, kh, kl, vh, vl);

    // 8: flash attention
    flash_mma<<<dim3(LL / 128, HH, BB), 256, FLASH_SMEM>>>(qh, ql, kh, kl, vh, vl, oh, ol);

    // 9-10: out projection
    split_bf16<<<(DD * DD) / 1024, 256>>>(W_out, woh, wol, DD * DD);
    gemm_mma<<<dim3(DD / 128, MM / 128), 256, GEMM_SMEM>>>(oh, ol, woh, wol, b_out, out, DD);
}

// round 12
// speedup vs baseline: 1.0630x; 1.0630x over previous
#include <cuda_runtime.h>
#include <cuda_bf16.h>
#include <cstdint>

#define BB 2
#define LL 2048
#define DD 1024
#define HH 16
#define HD 64
#define MM (BB*LL)          // 4096
#define E3 (3*DD)           // 3072
#define PH (DD/2)           // 512
#define GK DD               // GEMM K=1024

typedef unsigned long long ull;
typedef __nv_bfloat16 bf16;

// ---------------- scratch ----------------
__device__ float g_qkv[MM * E3];
__device__ float g_phases[MM * PH];
__device__ bf16 g_xh[MM*DD],  g_xl[MM*DD];
__device__ bf16 g_wqh[E3*DD], g_wql[E3*DD];
__device__ bf16 g_ph2[MM*DD], g_pl2[MM*DD];
__device__ bf16 g_pth[PH*DD], g_ptl[PH*DD];
__device__ bf16 g_oh[MM*DD],  g_ol[MM*DD];
__device__ bf16 g_woh[DD*DD], g_wol[DD*DD];
__device__ bf16 g_qh[MM*DD], g_ql[MM*DD];
__device__ bf16 g_kh[MM*DD], g_kl[MM*DD];
__device__ bf16 g_vh[MM*DD], g_vl[MM*DD];

// ---------------- PTX helpers ----------------
__device__ __forceinline__ uint32_t smem_u32(const void* p) {
    uint32_t a;
    asm("{ .reg .u64 t; cvta.to.shared.u64 t, %1; cvt.u32.u64 %0, t; }" : "=r"(a) : "l"(p));
    return a;
}
#define LDSM4(R, addr) \
    asm volatile("ldmatrix.sync.aligned.m8n8.x4.shared.b16 {%0,%1,%2,%3}, [%4];" \
        : "=r"((R)[0]), "=r"((R)[1]), "=r"((R)[2]), "=r"((R)[3]) : "r"(addr))
#define LDSM4T(R, addr) \
    asm volatile("ldmatrix.sync.aligned.m8n8.x4.trans.shared.b16 {%0,%1,%2,%3}, [%4];" \
        : "=r"((R)[0]), "=r"((R)[1]), "=r"((R)[2]), "=r"((R)[3]) : "r"(addr))
#define MMA16816(D, A, B0, B1) \
    asm volatile("mma.sync.aligned.m16n8k16.row.col.f32.bf16.bf16.f32 " \
        "{%0,%1,%2,%3}, {%4,%5,%6,%7}, {%8,%9}, {%0,%1,%2,%3};" \
        : "+f"((D)[0]), "+f"((D)[1]), "+f"((D)[2]), "+f"((D)[3]) \
        : "r"((A)[0]), "r"((A)[1]), "r"((A)[2]), "r"((A)[3]), "r"(B0), "r"(B1))
#define CPA16(dst, src) \
    asm volatile("cp.async.cg.shared.global [%0], [%1], 16;" :: "r"(dst), "l"(src))
#define CPA_COMMIT() asm volatile("cp.async.commit_group;" ::: "memory")
#define CPA_WAIT1()  asm volatile("cp.async.wait_group 1;" ::: "memory")
#define CPA_WAIT0()  asm volatile("cp.async.wait_group 0;" ::: "memory")

union BF2U { __nv_bfloat162 b; uint32_t u; };
__device__ __forceinline__ void split_pack2(float e0, float e1, uint32_t& hi, uint32_t& lo) {
    bf16 h0 = __float2bfloat16(e0), h1 = __float2bfloat16(e1);
    float r0 = e0 - __bfloat162float(h0), r1 = e1 - __bfloat162float(h1);
    BF2U a, b2;
    a.b  = __halves2bfloat162(h0, h1);
    b2.b = __halves2bfloat162(__float2bfloat16(r0), __float2bfloat16(r1));
    hi = a.u; lo = b2.u;
}

// ---------------------------------------------------------------------------
// prep_all: one launch does all input splits.
//   region 0: x     (MM*DD)  -> xh/xl        [float4 units]
//   region 1: W_qkv (E3*DD)  -> wqh/wql
//   region 2: p     (MM*DD)  -> ph2/pl2
//   region 3: W_out (DD*DD)  -> woh/wol
//   region 4: projT (PH*DD)  -> pth/ptl  (transposed gather)
// ---------------------------------------------------------------------------
#define R0 (MM*DD/4)                    // 1048576
#define R1 (R0 + E3*DD/4)               // 1835008
#define R2 (R1 + MM*DD/4)               // 2883584
#define R3 (R2 + DD*DD/4)               // 3145728
#define R4 (R3 + PH*DD/4)               // 3276800

__device__ __forceinline__ void split4_store(const float* __restrict__ src, int i,
                                             bf16* __restrict__ hi, bf16* __restrict__ lo)
{
    float4 v = *(const float4*)(src + i);
    uint32_t h0, l0, h1, l1;
    split_pack2(v.x, v.y, h0, l0);
    split_pack2(v.z, v.w, h1, l1);
    *(uint2*)(hi + i) = make_uint2(h0, h1);
    *(uint2*)(lo + i) = make_uint2(l0, l1);
}

__global__ void prep_all(const float* __restrict__ x, const float* __restrict__ p,
                         const float* __restrict__ W_qkv, const float* __restrict__ W_out,
                         const float* __restrict__ proj,
                         bf16* __restrict__ xh, bf16* __restrict__ xl,
                         bf16* __restrict__ wqh, bf16* __restrict__ wql,
                         bf16* __restrict__ ph2, bf16* __restrict__ pl2,
                         bf16* __restrict__ woh, bf16* __restrict__ wol,
                         bf16* __restrict__ pth, bf16* __restrict__ ptl)
{
    int u = blockIdx.x * blockDim.x + threadIdx.x;
    if (u < R0) {
        split4_store(x, u * 4, xh, xl);
    } else if (u < R1) {
        split4_store(W_qkv, (u - R0) * 4, wqh, wql);
    } else if (u < R2) {
        split4_store(p, (u - R1) * 4, ph2, pl2);
    } else if (u < R3) {
        split4_store(W_out, (u - R2) * 4, woh, wol);
    } else if (u < R4) {
        int o = (u - R3) * 4;          // output idx in (PH, D) row-major
        int j = o >> 10;
        int d0 = o & 1023;
        uint32_t h0, l0, h1, l1;
        float v0 = proj[(size_t)(d0 + 0) * PH + j];
        float v1 = proj[(size_t)(d0 + 1) * PH + j];
        float v2 = proj[(size_t)(d0 + 2) * PH + j];
        float v3 = proj[(size_t)(d0 + 3) * PH + j];
        split_pack2(v0, v1, h0, l0);
        split_pack2(v2, v3, h1, l1);
        *(uint2*)(pth + o) = make_uint2(h0, h1);
        *(uint2*)(ptl + o) = make_uint2(l0, l1);
    }
}

// ---------------------------------------------------------------------------
// HMMA NT GEMM: C = A @ B^T (+bias). Term-major ordering, 2-stage pipeline
// (R10 proven config: 2 CTAs/SM).
// ---------------------------------------------------------------------------
#define PITCH 40
#define BUF_B (128 * PITCH * 2)
#define STAGE_B (4 * BUF_B)
#define GEMM_SMEM (2 * STAGE_B)         // 81920
#define NKC (GK / 32)

__global__ __launch_bounds__(256) void gemm_mma(
    const bf16* __restrict__ Ahi, const bf16* __restrict__ Alo,
    const bf16* __restrict__ Bhi, const bf16* __restrict__ Blo,
    const float* __restrict__ bias, float* __restrict__ C, int N)
{
    extern __shared__ char smem[];
    const uint32_t sb = smem_u32(smem);
    const int tid = threadIdx.x;
    const int lane = tid & 31;
    const int wid = tid >> 5;
    const int warp_m = wid >> 1;
    const int warp_n = wid & 1;
    const int bm = blockIdx.y * 128;
    const int bn = blockIdx.x * 128;

    const int lr = tid >> 1;
    const int lh = tid & 1;
    const bf16* gAh = Ahi + (size_t)(bm + lr) * GK + lh * 16;
    const bf16* gAl = Alo + (size_t)(bm + lr) * GK + lh * 16;
    const bf16* gBh = Bhi + (size_t)(bn + lr) * GK + lh * 16;
    const bf16* gBl = Blo + (size_t)(bn + lr) * GK + lh * 16;
    const uint32_t srow = sb + (uint32_t)(lr * PITCH + lh * 16) * 2;

    auto issue_stage = [&](int kc, int s) {
        const uint32_t st = srow + s * STAGE_B;
        const size_t go = (size_t)kc * 32;
        CPA16(st + 0 * BUF_B,      gAh + go);
        CPA16(st + 0 * BUF_B + 16, gAh + go + 8);
        CPA16(st + 1 * BUF_B,      gAl + go);
        CPA16(st + 1 * BUF_B + 16, gAl + go + 8);
        CPA16(st + 2 * BUF_B,      gBh + go);
        CPA16(st + 2 * BUF_B + 16, gBh + go + 8);
        CPA16(st + 3 * BUF_B,      gBl + go);
        CPA16(st + 3 * BUF_B + 16, gBl + go + 8);
    };

    float acc[2][8][4];
    #pragma unroll
    for (int mt = 0; mt < 2; mt++)
        #pragma unroll
        for (int nt = 0; nt < 8; nt++)
            #pragma unroll
            for (int e = 0; e < 4; e++) acc[mt][nt][e] = 0.f;

    const int lrow = lane & 15;
    const int lsub = lane >> 4;

    issue_stage(0, 0);
    CPA_COMMIT();

    for (int kc = 0; kc < NKC; kc++) {
        const int cur = kc & 1;
        if (kc + 1 < NKC) {
            issue_stage(kc + 1, cur ^ 1);
            CPA_COMMIT();
            CPA_WAIT1();
        } else {
            CPA_WAIT0();
        }
        __syncthreads();

        const uint32_t stA_hi = sb + cur * STAGE_B;
        const uint32_t stA_lo = stA_hi + BUF_B;
        const uint32_t stB_hi = stA_hi + 2 * BUF_B;
        const uint32_t stB_lo = stA_hi + 3 * BUF_B;

        #pragma unroll
        for (int h = 0; h < 2; h++) {
            const uint32_t coff = (uint32_t)(h * 16 + lsub * 8) * 2;
            uint32_t ah[2][4], al[2][4];
            #pragma unroll
            for (int mt = 0; mt < 2; mt++) {
                const uint32_t ro = (uint32_t)((warp_m * 32 + mt * 16 + lrow) * PITCH) * 2 + coff;
                LDSM4(ah[mt], stA_hi + ro);
                LDSM4(al[mt], stA_lo + ro);
            }
            uint32_t bh[4][4], bl[4][4];
            #pragma unroll
            for (int g = 0; g < 4; g++) {
                const uint32_t ro = (uint32_t)((warp_n * 64 + g * 16 + lrow) * PITCH) * 2 + coff;
                LDSM4(bh[g], stB_hi + ro);
                LDSM4(bl[g], stB_lo + ro);
            }
            #pragma unroll
            for (int mt = 0; mt < 2; mt++)
                #pragma unroll
                for (int g = 0; g < 4; g++)
                    #pragma unroll
                    for (int s2 = 0; s2 < 2; s2++)
                        MMA16816(acc[mt][g * 2 + s2], ah[mt], bh[g][s2], bh[g][s2 + 2]);
            #pragma unroll
            for (int mt = 0; mt < 2; mt++)
                #pragma unroll
                for (int g = 0; g < 4; g++)
                    #pragma unroll
                    for (int s2 = 0; s2 < 2; s2++)
                        MMA16816(acc[mt][g * 2 + s2], ah[mt], bl[g][s2], bl[g][s2 + 2]);
            #pragma unroll
            for (int mt = 0; mt < 2; mt++)
                #pragma unroll
                for (int g = 0; g < 4; g++)
                    #pragma unroll
                    for (int s2 = 0; s2 < 2; s2++)
                        MMA16816(acc[mt][g * 2 + s2], al[mt], bh[g][s2], bh[g][s2 + 2]);
        }
        __syncthreads();
    }

    const int gid = lane >> 2;
    const int tig = lane & 3;
    #pragma unroll
    for (int mt = 0; mt < 2; mt++) {
        const int r0 = bm + warp_m * 32 + mt * 16 + gid;
        #pragma unroll
        for (int nt = 0; nt < 8; nt++) {
            const int c0 = bn + warp_n * 64 + nt * 8 + tig * 2;
            float b0 = bias ? bias[c0] : 0.f;
            float b1 = bias ? bias[c0 + 1] : 0.f;
            *(float2*)&C[(size_t)r0 * N + c0] =
                make_float2(acc[mt][nt][0] + b0, acc[mt][nt][1] + b1);
            *(float2*)&C[(size_t)(r0 + 8) * N + c0] =
                make_float2(acc[mt][nt][2] + b0, acc[mt][nt][3] + b1);
        }
    }
}

// ---------------------------------------------------------------------------
// RoPE + split, vectorized: 2 columns per thread.
// ---------------------------------------------------------------------------
__global__ void rope_split(const float* __restrict__ qkv, const float* __restrict__ phases,
                           bf16* __restrict__ qh, bf16* __restrict__ ql,
                           bf16* __restrict__ kh, bf16* __restrict__ kl,
                           bf16* __restrict__ vh, bf16* __restrict__ vl)
{
    int idx = blockIdx.x * blockDim.x + threadIdx.x;   // MM*PH/2
    int m = idx >> 8;
    int r = idx & 255;
    int h = r >> 4;
    int j0 = (r & 15) * 2;
    const float2 ph2 = *(const float2*)(phases + (size_t)m * PH + h * 32 + j0);
    float s0, c0, s1, c1;
    __sincosf(ph2.x, &s0, &c0);
    __sincosf(ph2.y, &s1, &c1);
    size_t ib = (size_t)m * E3 + h * HD + j0;
    size_t ob = (size_t)m * DD + h * HD + j0;
    uint32_t hi, lo;

    float2 q1 = *(const float2*)(qkv + ib);
    float2 q2 = *(const float2*)(qkv + ib + 32);
    split_pack2((q1.x * c0 - q2.x * s0) * 0.125f, (q1.y * c1 - q2.y * s1) * 0.125f, hi, lo);
    *(uint32_t*)(qh + ob) = hi; *(uint32_t*)(ql + ob) = lo;
    split_pack2((q1.x * s0 + q2.x * c0) * 0.125f, (q1.y * s1 + q2.y * c1) * 0.125f, hi, lo);
    *(uint32_t*)(qh + ob + 32) = hi; *(uint32_t*)(ql + ob + 32) = lo;

    float2 k1 = *(const float2*)(qkv + ib + DD);
    float2 k2 = *(const float2*)(qkv + ib + DD + 32);
    split_pack2(k1.x * c0 - k2.x * s0, k1.y * c1 - k2.y * s1, hi, lo);
    *(uint32_t*)(kh + ob) = hi; *(uint32_t*)(kl + ob) = lo;
    split_pack2(k1.x * s0 + k2.x * c0, k1.y * s1 + k2.y * c1, hi, lo);
    *(uint32_t*)(kh + ob + 32) = hi; *(uint32_t*)(kl + ob + 32) = lo;

    float2 v1 = *(const float2*)(qkv + ib + 2 * DD);
    float2 v2 = *(const float2*)(qkv + ib + 2 * DD + 32);
    split_pack2(v1.x, v1.y, hi, lo);
    *(uint32_t*)(vh + ob) = hi; *(uint32_t*)(vl + ob) = lo;
    split_pack2(v2.x, v2.y, hi, lo);
    *(uint32_t*)(vh + ob + 32) = hi; *(uint32_t*)(vl + ob + 32) = lo;
}

// ---------------------------------------------------------------------------
// HMMA flash attention (unchanged)
// ---------------------------------------------------------------------------
#define FROWB 144
#define FQH 0
#define FQL 18432
#define FKV 36864
#define FSTG 36864
#define F_KH 0
#define F_KL 9216
#define F_VH 18432
#define F_VL 27648
#define FLASH_SMEM (FKV + 2 * FSTG)   // 110592 B

__global__ __launch_bounds__(256) void flash_mma(
    const bf16* __restrict__ qh_g, const bf16* __restrict__ ql_g,
    const bf16* __restrict__ kh_g, const bf16* __restrict__ kl_g,
    const bf16* __restrict__ vh_g, const bf16* __restrict__ vl_g,
    bf16* __restrict__ oh_g, bf16* __restrict__ ol_g)
{
    extern __shared__ char smem[];
    const uint32_t sb = smem_u32(smem);
    const int tid = threadIdx.x;
    const int lane = tid & 31;
    const int warp = tid >> 5;
    const int b = blockIdx.z, h = blockIdx.y, qt = blockIdx.x;

    const size_t qrow0 = (size_t)b * LL + qt * 128;
    const size_t krow0 = (size_t)b * LL;
    const int hcol = h * HD;

    const int qlr = tid >> 1;
    const int qlc = (tid & 1) * 4;
    const uint32_t qdst = (uint32_t)(qlr * FROWB + qlc * 16);
    const size_t qsrc = (size_t)qlr * DD + hcol + qlc * 8;
    const int klr = tid >> 2;
    const int klc = (tid & 3) * 2;
    const uint32_t kdst = (uint32_t)(klr * FROWB + klc * 16);
    const size_t ksrc = (size_t)klr * DD + hcol + klc * 8;

    auto issue_kv = [&](int kt, int s) {
        const uint32_t st = sb + FKV + s * FSTG + kdst;
        const size_t go = (size_t)kt * 64 * DD + krow0 * DD + ksrc;
        CPA16(st + F_KH,      kh_g + go);
        CPA16(st + F_KH + 16, kh_g + go + 8);
        CPA16(st + F_KL,      kl_g + go);
        CPA16(st + F_KL + 16, kl_g + go + 8);
        CPA16(st + F_VH,      vh_g + go);
        CPA16(st + F_VH + 16, vh_g + go + 8);
        CPA16(st + F_VL,      vl_g + go);
        CPA16(st + F_VL + 16, vl_g + go + 8);
    };

    {
        const bf16* s0 = qh_g + qrow0 * DD + qsrc;
        const bf16* s1 = ql_g + qrow0 * DD + qsrc;
        CPA16(sb + FQH + qdst,      s0);      CPA16(sb + FQH + qdst + 16, s0 + 8);
        CPA16(sb + FQH + qdst + 32, s0 + 16); CPA16(sb + FQH + qdst + 48, s0 + 24);
        CPA16(sb + FQL + qdst,      s1);      CPA16(sb + FQL + qdst + 16, s1 + 8);
        CPA16(sb + FQL + qdst + 32, s1 + 16); CPA16(sb + FQL + qdst + 48, s1 + 24);
    }
    issue_kv(0, 0);
    CPA_COMMIT();

    const int lrow = lane & 15;
    const int lsub = lane >> 4;
    const int gid = lane >> 2;
    const int tig = lane & 3;

    uint32_t qfh[4][4], qfl[4][4];
    float o[8][4];
    #pragma unroll
    for (int nt = 0; nt < 8; nt++)
        #pragma unroll
        for (int e = 0; e < 4; e++) o[nt][e] = 0.f;
    float m_a = -1e30f, m_b = -1e30f, l_a = 0.f, l_b = 0.f;

    for (int kt = 0; kt < LL / 64; kt++) {
        const int cur = kt & 1;
        if (kt + 1 < LL / 64) {
            issue_kv(kt + 1, cur ^ 1);
            CPA_COMMIT();
            CPA_WAIT1();
        } else {
            CPA_WAIT0();
        }
        __syncthreads();

        if (kt == 0) {
            #pragma unroll
            for (int ks = 0; ks < 4; ks++) {
                const uint32_t ro = (uint32_t)((warp * 16 + lrow) * FROWB + (ks * 16 + lsub * 8) * 2);
                LDSM4(qfh[ks], sb + FQH + ro);
                LDSM4(qfl[ks], sb + FQL + ro);
            }
        }

        const uint32_t kb = sb + FKV + cur * FSTG;

        float s[8][4];
        #pragma unroll
        for (int nt = 0; nt < 8; nt++)
            #pragma unroll
            for (int e = 0; e < 4; e++) s[nt][e] = 0.f;

        #pragma unroll
        for (int ks = 0; ks < 4; ks++) {
            uint32_t kfh[4][4], kfl[4][4];
            #pragma unroll
            for (int kg = 0; kg < 4; kg++) {
                const uint32_t ro = (uint32_t)((kg * 16 + lrow) * FROWB + (ks * 16 + lsub * 8) * 2);
                LDSM4(kfh[kg], kb + F_KH + ro);
                LDSM4(kfl[kg], kb + F_KL + ro);
            }
            #pragma unroll
            for (int kg = 0; kg < 4; kg++) {
                MMA16816(s[2 * kg],     qfh[ks], kfh[kg][0], kfh[kg][2]);
                MMA16816(s[2 * kg + 1], qfh[ks], kfh[kg][1], kfh[kg][3]);
            }
            #pragma unroll
            for (int kg = 0; kg < 4; kg++) {
                MMA16816(s[2 * kg],     qfh[ks], kfl[kg][0], kfl[kg][2]);
                MMA16816(s[2 * kg + 1], qfh[ks], kfl[kg][1], kfl[kg][3]);
            }
            #pragma unroll
            for (int kg = 0; kg < 4; kg++) {
                MMA16816(s[2 * kg],     qfl[ks], kfh[kg][0], kfh[kg][2]);
                MMA16816(s[2 * kg + 1], qfl[ks], kfh[kg][1], kfh[kg][3]);
            }
        }

        float mx_a = -1e30f, mx_b = -1e30f;
        #pragma unroll
        for (int nt = 0; nt < 8; nt++) {
            mx_a = fmaxf(mx_a, fmaxf(s[nt][0], s[nt][1]));
            mx_b = fmaxf(mx_b, fmaxf(s[nt][2], s[nt][3]));
        }
        #pragma unroll
        for (int off = 1; off <= 2; off <<= 1) {
            mx_a = fmaxf(mx_a, __shfl_xor_sync(0xffffffffu, mx_a, off));
            mx_b = fmaxf(mx_b, __shfl_xor_sync(0xffffffffu, mx_b, off));
        }
        const float mn_a = fmaxf(m_a, mx_a);
        const float mn_b = fmaxf(m_b, mx_b);
        const float sf_a = __expf(m_a - mn_a);
        const float sf_b = __expf(m_b - mn_b);
        m_a = mn_a; m_b = mn_b;

        float rs_a = 0.f, rs_b = 0.f;
        #pragma unroll
        for (int nt = 0; nt < 8; nt++) {
            s[nt][0] = __expf(s[nt][0] - mn_a);
            s[nt][1] = __expf(s[nt][1] - mn_a);
            s[nt][2] = __expf(s[nt][2] - mn_b);
            s[nt][3] = __expf(s[nt][3] - mn_b);
            rs_a += s[nt][0] + s[nt][1];
            rs_b += s[nt][2] + s[nt][3];
        }
        #pragma unroll
        for (int off = 1; off <= 2; off <<= 1) {
            rs_a += __shfl_xor_sync(0xffffffffu, rs_a, off);
            rs_b += __shfl_xor_sync(0xffffffffu, rs_b, off);
        }
        l_a = l_a * sf_a + rs_a;
        l_b = l_b * sf_b + rs_b;
        #pragma unroll
        for (int nt = 0; nt < 8; nt++) {
            o[nt][0] *= sf_a; o[nt][1] *= sf_a;
            o[nt][2] *= sf_b; o[nt][3] *= sf_b;
        }

        uint32_t ph[4][4], pl[4][4];
        #pragma unroll
        for (int kg = 0; kg < 4; kg++) {
            split_pack2(s[2 * kg][0],     s[2 * kg][1],     ph[kg][0], pl[kg][0]);
            split_pack2(s[2 * kg][2],     s[2 * kg][3],     ph[kg][1], pl[kg][1]);
            split_pack2(s[2 * kg + 1][0], s[2 * kg + 1][1], ph[kg][2], pl[kg][2]);
            split_pack2(s[2 * kg + 1][2], s[2 * kg + 1][3], ph[kg][3], pl[kg][3]);
        }

        #pragma unroll
        for (int kg = 0; kg < 4; kg++) {
            uint32_t vfh[4][4], vfl[4][4];
            #pragma unroll
            for (int dg = 0; dg < 4; dg++) {
                const uint32_t ro = (uint32_t)((kg * 16 + lrow) * FROWB + (dg * 16 + lsub * 8) * 2);
                LDSM4T(vfh[dg], kb + F_VH + ro);
                LDSM4T(vfl[dg], kb + F_VL + ro);
            }
            #pragma unroll
            for (int dg = 0; dg < 4; dg++) {
                MMA16816(o[2 * dg],     ph[kg], vfh[dg][0], vfh[dg][1]);
                MMA16816(o[2 * dg + 1], ph[kg], vfh[dg][2], vfh[dg][3]);
            }
            #pragma unroll
            for (int dg = 0; dg < 4; dg++) {
                MMA16816(o[2 * dg],     ph[kg], vfl[dg][0], vfl[dg][1]);
                MMA16816(o[2 * dg + 1], ph[kg], vfl[dg][2], vfl[dg][3]);
            }
            #pragma unroll
            for (int dg = 0; dg < 4; dg++) {
                MMA16816(o[2 * dg],     pl[kg], vfh[dg][0], vfh[dg][1]);
                MMA16816(o[2 * dg + 1], pl[kg], vfh[dg][2], vfh[dg][3]);
            }
        }
        __syncthreads();
    }

    const float inv_a = 1.0f / l_a;
    const float inv_b = 1.0f / l_b;
    const size_t row_a = qrow0 + warp * 16 + gid;
    const size_t row_b = row_a + 8;
    #pragma unroll
    for (int nt = 0; nt < 8; nt++) {
        const int col = hcol + nt * 8 + tig * 2;
        uint32_t hi, lo;
        split_pack2(o[nt][0] * inv_a, o[nt][1] * inv_a, hi, lo);
        *(uint32_t*)(oh_g + row_a * DD + col) = hi;
        *(uint32_t*)(ol_g + row_a * DD + col) = lo;
        split_pack2(o[nt][2] * inv_b, o[nt][3] * inv_b, hi, lo);
        *(uint32_t*)(oh_g + row_b * DD + col) = hi;
        *(uint32_t*)(ol_g + row_b * DD + col) = lo;
    }
}

// ---------------------------------------------------------------------------
extern "C" void kernel_launch(void* const* d_in, const int* in_sizes, int n_in,
                              void* d_out, int out_size)
{
    const float* x     = (const float*)d_in[0];
    const float* p     = (const float*)d_in[1];
    const float* W_qkv = (const float*)d_in[2];
    const float* b_qkv = (const float*)d_in[3];
    const float* W_out = (const float*)d_in[4];
    const float* b_out = (const float*)d_in[5];
    const float* proj  = (const float*)d_in[6];
    float* out = (float*)d_out;

    float *qkv, *phases;
    cudaGetSymbolAddress((void**)&qkv,    g_qkv);
    cudaGetSymbolAddress((void**)&phases, g_phases);
    bf16 *xh, *xl, *wqh, *wql, *ph2, *pl2, *pth, *ptl, *oh, *ol, *woh, *wol;
    bf16 *qh, *ql, *kh, *kl, *vh, *vl;
    cudaGetSymbolAddress((void**)&xh,  g_xh);  cudaGetSymbolAddress((void**)&xl,  g_xl);
    cudaGetSymbolAddress((void**)&wqh, g_wqh); cudaGetSymbolAddress((void**)&wql, g_wql);
    cudaGetSymbolAddress((void**)&ph2, g_ph2); cudaGetSymbolAddress((void**)&pl2, g_pl2);
    cudaGetSymbolAddress((void**)&pth, g_pth); cudaGetSymbolAddress((void**)&ptl, g_ptl);
    cudaGetSymbolAddress((void**)&oh,  g_oh);  cudaGetSymbolAddress((void**)&ol,  g_ol);
    cudaGetSymbolAddress((void**)&woh, g_woh); cudaGetSymbolAddress((void**)&wol, g_wol);
    cudaGetSymbolAddress((void**)&qh, g_qh); cudaGetSymbolAddress((void**)&ql, g_ql);
    cudaGetSymbolAddress((void**)&kh, g_kh); cudaGetSymbolAddress((void**)&kl, g_kl);
    cudaGetSymbolAddress((void**)&vh, g_vh); cudaGetSymbolAddress((void**)&vl, g_vl);

    cudaFuncSetAttribute(gemm_mma, cudaFuncAttributeMaxDynamicSharedMemorySize, GEMM_SMEM);
    cudaFuncSetAttribute(flash_mma, cudaFuncAttributeMaxDynamicSharedMemorySize, FLASH_SMEM);

    // 1: all input splits in one launch
    prep_all<<<R4 / 256, 256>>>(x, p, W_qkv, W_out, proj,
                                xh, xl, wqh, wql, ph2, pl2, woh, wol, pth, ptl);

    // 2: QKV GEMM
    gemm_mma<<<dim3(E3 / 128, MM / 128), 256, GEMM_SMEM>>>(xh, xl, wqh, wql, b_qkv, qkv, E3);

    // 3: phases GEMM
    gemm_mma<<<dim3(PH / 128, MM / 128), 256, GEMM_SMEM>>>(ph2, pl2, pth, ptl, nullptr, phases, PH);

    // 4: rope + split (profiled slot)
    rope_split<<<(MM * PH / 2) / 256, 256>>>(qkv, phases, qh, ql, kh, kl, vh, vl);

    // 5: flash attention
    flash_mma<<<dim3(LL / 128, HH, BB), 256, FLASH_SMEM>>>(qh, ql, kh, kl, vh, vl, oh, ol);

    // 6: out projection
    gemm_mma<<<dim3(DD / 128, MM / 128), 256, GEMM_SMEM>>>(oh, ol, woh, wol, b_out, out, DD);
}